// round 16
// baseline (speedup 1.0000x reference)
#include <cuda_runtime.h>
#include <cuda_fp16.h>
#include <cstdint>
#include <math.h>

// Problem dims (fixed by the dataset)
#define T_STEPS 4
#define B_SZ    16
#define TBDIM   64               // T*B
#define NDIM    1024
#define CC      768              // channels (in == out)
#define M_ROWS  (TBDIM * NDIM)   // 65536
#define JBLK    (NDIM * CC)      // 786432 elements per tb block

#define NPART 1024               // one stats partial per (channel, 64-row m-tile)

// ---------------- scratch (static device globals; no runtime alloc) ----------
__device__ float  g_y[(size_t)M_ROWS * CC];         // 201 MB GEMM output
__device__ __half g_wp[2][(size_t)CC * CC];         // 2.3 MB split planes of W
__device__ float  g_psum[CC * NPART];
__device__ float  g_psq [CC * NPART];
__device__ float  g_mean[CC];
__device__ float  g_rstd[CC];

// =================== low-level helpers (base ISA only) =======================
__device__ __forceinline__ uint32_t smem_u32(const void* p) {
    uint32_t a;
    asm("{ .reg .u64 t; cvta.to.shared.u64 t, %1; cvt.u32.u64 %0, t; }" : "=r"(a) : "l"(p));
    return a;
}
__device__ __forceinline__ uint32_t swz(uint32_t o) {   // SW128: XOR bits[6:4] ^= bits[9:7]
    return o ^ ((o >> 3) & 0x70);
}
__device__ __forceinline__ uint32_t h2u(__half2 h) {
    return *reinterpret_cast<uint32_t*>(&h);
}
#define CP_ASYNC16(dst, src) \
    asm volatile("cp.async.cg.shared.global [%0], [%1], 16;" :: "r"(dst), "l"(src))
#define CP_COMMIT() asm volatile("cp.async.commit_group;" ::: "memory")
#define CP_WAIT0()  asm volatile("cp.async.wait_group 0;" ::: "memory")

#define LDSM4(r, addr)                                                          \
    asm volatile("ldmatrix.sync.aligned.m8n8.x4.shared.b16 {%0,%1,%2,%3}, [%4];"\
        : "=r"((r)[0]), "=r"((r)[1]), "=r"((r)[2]), "=r"((r)[3]) : "r"(addr))

#define MMA16816(c, a, bb0, bb1)                                                \
    asm volatile("mma.sync.aligned.m16n8k16.row.col.f32.f16.f16.f32 "           \
                 "{%0,%1,%2,%3}, {%4,%5,%6,%7}, {%8,%9}, {%0,%1,%2,%3};"        \
        : "+f"((c)[0]), "+f"((c)[1]), "+f"((c)[2]), "+f"((c)[3])                \
        : "r"((a)[0]), "r"((a)[1]), "r"((a)[2]), "r"((a)[3]), "r"(bb0), "r"(bb1))

// =================== Kernel 0: exact 2-way fp16 split (W only) ===============
__global__ __launch_bounds__(256)
void split2_w(const float* __restrict__ src, int n4)
{
    const int i = blockIdx.x * 256 + threadIdx.x;
    if (i >= n4) return;
    const float4 v = ((const float4*)src)[i];
    float2 p0 = make_float2(v.x, v.y);
    float2 p1 = make_float2(v.z, v.w);
    __half2 a0 = __float22half2_rn(p0);
    __half2 a1 = __float22half2_rn(p1);
    float2 f0 = __half22float2(a0);
    float2 f1 = __half22float2(a1);
    float2 r0 = make_float2(__fsub_rn(p0.x, f0.x), __fsub_rn(p0.y, f0.y));
    float2 r1 = make_float2(__fsub_rn(p1.x, f1.x), __fsub_rn(p1.y, f1.y));
    __half2 b0 = __float22half2_rn(r0);
    __half2 b1 = __float22half2_rn(r1);
    ((uint2*)g_wp[0])[i] = make_uint2(h2u(a0), h2u(a1));
    ((uint2*)g_wp[1])[i] = make_uint2(h2u(b0), h2u(b1));
}

// =================== Kernel 1: fused split + fp16x3 GEMM + stats =============
// Y[m][n] = sum_k X[m][k] * W[n][k].  CTA tile 64x128 (M x N), 12 K-stages of 64.
// 256 threads, 8 warps, warp tile 32x32 (2x4 warp grid), 2 CTAs per SM.
// X LDG prefetched into registers in two halves (before j=0 and before j=2);
// packed convert after the MMA block; fold before the cp.async wait.
// Swizzle strength reduction: power-of-2 plane/buffer strides are affine; the
// j*32 k-step offset applies via XOR.
// SMEM: A fp16 planes ring2 (32K) | B planes ring2 (64K) = 96 KB.
#define GM 64
#define GN 128
#define NTHR 256
#define SM_A_OFF   0
#define SM_B_OFF   32768
#define SMEM_GEMM  98304        // 96 KB -> 2 CTAs/SM

__global__ __launch_bounds__(NTHR, 2)
void gemm_fused(const float* __restrict__ X)
{
    extern __shared__ __align__(1024) char smem[];
    const uint32_t sb = smem_u32(smem);
    const int tid  = threadIdx.x;
    const int lane = tid & 31;
    const int wid  = tid >> 5;          // 0..7

    const int n0 = blockIdx.x * GN;     // 0..5    -> channel strip
    const int m0 = blockIdx.y * GM;     // 0..1023 -> 64-row tile
    const int bm = blockIdx.y;
    const int m0w = (wid >> 2) * 32;    // warp tile 32x32 (2 m-halves)
    const int n0w = (wid & 3) * 32;

    float accM[2][4][4];
    float accT[2][4][4];
#pragma unroll
    for (int i = 0; i < 2; i++)
#pragma unroll
        for (int j = 0; j < 4; j++)
#pragma unroll
            for (int k = 0; k < 4; k++) { accM[i][j][k] = 0.f; accT[i][j][k] = 0.f; }

    // ---- strength-reduced base addresses ------------------------------------
    const int rA = m0w + (lane & 15);
    const uint32_t cA = (uint32_t)((lane >> 4) * 16);
    const int rB = n0w + (lane & 7) + ((lane >> 4) << 3);
    const uint32_t cB = (uint32_t)(((lane >> 3) & 1) * 16);
    const uint32_t swzA0 = swz((uint32_t)(rA * 128) + cA);
    const uint32_t swzB0 = swz((uint32_t)(rB * 128) + cB);

    // issueB: it 0..3 -> plane0 rows rowB0+32it; it 4..7 -> plane1 same rows
    const int chB   = tid & 7;
    const int rowB0 = (tid >> 3) & 127;              // 0..31
    const __half* srcB0 = &g_wp[0][(size_t)(n0 + rowB0) * CC + chB * 8];
    const __half* srcB1 = &g_wp[1][(size_t)(n0 + rowB0) * CC + chB * 8];
    const uint32_t dstB0 = swz((uint32_t)(rowB0 * 128 + chB * 16));  // +4096/it

    // ldgX / convert: it 0..3 -> rows rowX0+16it
    const int chX   = tid & 15;
    const int rowX0 = tid >> 4;                      // 0..15
    const float* srcX0 = &X[(size_t)(m0 + rowX0) * CC + chX * 4];
    const uint32_t dstA0 = swz((uint32_t)(rowX0 * 128 + chX * 8));   // +2048/it

    // ---- B planes via cp.async (strength-reduced addressing) ----
    auto issueB = [&](int k) {
        if (k <= 11) {
            const size_t koff = (size_t)(k * 64);
            const uint32_t bplb = sb + SM_B_OFF + (uint32_t)(k & 1) * 32768 + dstB0;
            const __half* s0 = srcB0 + koff;
            const __half* s1 = srcB1 + koff;
#pragma unroll
            for (int it = 0; it < 4; it++)
                CP_ASYNC16(bplb + (uint32_t)it * 4096, s0 + (size_t)it * 32 * CC);
#pragma unroll
            for (int it = 0; it < 4; it++)
                CP_ASYNC16(bplb + 16384u + (uint32_t)it * 4096, s1 + (size_t)it * 32 * CC);
        }
        CP_COMMIT();                                 // empty commits count too
    };

    // ---- X prefetch: 2 LDG.128 per call (half = 0 or 1) ----
    auto ldgX_half = [&](int s1, float4* xr, int half) {
        const float* s = srcX0 + (size_t)(s1 * 64);
#pragma unroll
        for (int it = half * 2; it < half * 2 + 2; it++)
            xr[it] = *(const float4*)(s + (size_t)it * 16 * CC);
    };

    // ---- packed split -> A1/A2 fp16 plane STS (bit-identical to scalar) -----
    auto convertStore = [&](int s1, const float4* xr) {
        char* ap = smem + SM_A_OFF + (size_t)(s1 & 1) * 16384;
#pragma unroll
        for (int it = 0; it < 4; it++) {
            float2 p0 = make_float2(xr[it].x, xr[it].y);
            float2 p1 = make_float2(xr[it].z, xr[it].w);
            __half2 a0 = __float22half2_rn(p0);
            __half2 a1 = __float22half2_rn(p1);
            float2 f0 = __half22float2(a0);
            float2 f1 = __half22float2(a1);
            float2 r0 = make_float2(__fsub_rn(p0.x, f0.x), __fsub_rn(p0.y, f0.y));
            float2 r1 = make_float2(__fsub_rn(p1.x, f1.x), __fsub_rn(p1.y, f1.y));
            __half2 b0 = __float22half2_rn(r0);
            __half2 b1 = __float22half2_rn(r1);
            const uint32_t o = dstA0 + (uint32_t)it * 2048;
            *(uint2*)(ap + o)        = make_uint2(h2u(a0), h2u(a1));
            *(uint2*)(ap + 8192 + o) = make_uint2(h2u(b0), h2u(b1));
        }
    };

    // ---- prologue ----
    float4 xreg[4];
    issueB(0);
    ldgX_half(0, xreg, 0);
    ldgX_half(0, xreg, 1);
    CP_WAIT0();            // B(0) done
    convertStore(0, xreg);

    // ---- main loop: LDG halves straddle the MMA block; convert after ----
    for (int s = 0; s < 12; s++) {
        __syncthreads();                   // A(s&1)/B(s&1) visible; WAR safe
        issueB(s + 1);                     // pending: s+1 only (ring2)
        if (s < 11) ldgX_half(s + 1, xreg, 0);

        const uint32_t aBase = sb + SM_A_OFF + (uint32_t)(s & 1) * 16384 + swzA0;
        const uint32_t bBase = sb + SM_B_OFF + (uint32_t)(s & 1) * 32768 + swzB0;

#pragma unroll
        for (int j = 0; j < 4; j++) {      // k16 steps within stage
            const uint32_t jo = (uint32_t)(j * 32);
            uint32_t a1[2][4], a2[2][4], b1f[2][4], b2f[2][4];
#pragma unroll
            for (int i = 0; i < 2; i++)
                LDSM4(a1[i], (aBase + (uint32_t)i * 2048) ^ jo);
#pragma unroll
            for (int h = 0; h < 2; h++) {
                LDSM4(b1f[h], (bBase + (uint32_t)h * 2048) ^ jo);
                LDSM4(b2f[h], (bBase + 16384u + (uint32_t)h * 2048) ^ jo);
            }
#pragma unroll
            for (int i = 0; i < 2; i++)
#pragma unroll
                for (int h = 0; h < 2; h++) {
                    MMA16816(accT[i][2 * h],     a1[i], b1f[h][0], b1f[h][1]);
                    MMA16816(accT[i][2 * h + 1], a1[i], b1f[h][2], b1f[h][3]);
                }
#pragma unroll
            for (int i = 0; i < 2; i++)
#pragma unroll
                for (int h = 0; h < 2; h++) {
                    MMA16816(accT[i][2 * h],     a1[i], b2f[h][0], b2f[h][1]);
                    MMA16816(accT[i][2 * h + 1], a1[i], b2f[h][2], b2f[h][3]);
                }
#pragma unroll
            for (int i = 0; i < 2; i++)
                LDSM4(a2[i], (aBase + 8192u + (uint32_t)i * 2048) ^ jo);
#pragma unroll
            for (int i = 0; i < 2; i++)
#pragma unroll
                for (int h = 0; h < 2; h++) {
                    MMA16816(accT[i][2 * h],     a2[i], b1f[h][0], b1f[h][1]);
                    MMA16816(accT[i][2 * h + 1], a2[i], b1f[h][2], b1f[h][3]);
                }
            if (j == 1 && s < 11) ldgX_half(s + 1, xreg, 1);
        }

        if (s < 11) convertStore(s + 1, xreg);   // regs already landed

        // fold stage partial into persistent accumulator (independent of cp.async)
#pragma unroll
        for (int i = 0; i < 2; i++)
#pragma unroll
            for (int jn = 0; jn < 4; jn++)
#pragma unroll
                for (int k = 0; k < 4; k++) {
                    accM[i][jn][k] = __fadd_rn(accM[i][jn][k], accT[i][jn][k]);
                    accT[i][jn][k] = 0.f;
                }

        CP_WAIT0();                              // B(s+1) landed
    }

    // ---- epilogue 1: store y ----
#pragma unroll
    for (int i = 0; i < 2; i++)
#pragma unroll
        for (int jn = 0; jn < 4; jn++) {
            const int row = m0 + m0w + i * 16 + (lane >> 2);
            const int col = n0 + n0w + jn * 8 + 2 * (lane & 3);
            float2 v0 = make_float2(accM[i][jn][0], accM[i][jn][1]);
            float2 v1 = make_float2(accM[i][jn][2], accM[i][jn][3]);
            *(float2*)&g_y[(size_t)row * CC + col]       = v0;
            *(float2*)&g_y[(size_t)(row + 8) * CC + col] = v1;
        }

    // ---- epilogue 2: per-column sum / sumsq over this CTA's 64 rows ---------
    float cs[4][2], cq[4][2];
#pragma unroll
    for (int jn = 0; jn < 4; jn++)
#pragma unroll
        for (int p = 0; p < 2; p++) { cs[jn][p] = 0.f; cq[jn][p] = 0.f; }
#pragma unroll
    for (int i = 0; i < 2; i++)
#pragma unroll
        for (int jn = 0; jn < 4; jn++) {
#pragma unroll
            for (int p = 0; p < 2; p++) {
                const float v0 = accM[i][jn][p];        // row lane>>2
                const float v1 = accM[i][jn][p + 2];    // row lane>>2 + 8
                cs[jn][p] += v0 + v1;
                cq[jn][p] = __fmaf_rn(v0, v0, cq[jn][p]);
                cq[jn][p] = __fmaf_rn(v1, v1, cq[jn][p]);
            }
        }
    // butterfly over the 8 lanes sharing (lane & 3): offsets 4, 8, 16
#pragma unroll
    for (int r = 4; r <= 16; r <<= 1)
#pragma unroll
        for (int jn = 0; jn < 4; jn++)
#pragma unroll
            for (int p = 0; p < 2; p++) {
                cs[jn][p] += __shfl_xor_sync(0xffffffffu, cs[jn][p], r);
                cq[jn][p] += __shfl_xor_sync(0xffffffffu, cq[jn][p], r);
            }
    // stage per-warp column sums in smem (reuse A-plane area; idle now)
    float* st = (float*)(smem + SM_A_OFF);              // [2][128][2]
    __syncthreads();                                    // all MMA/convert done
    if (lane < 4) {
        const int mh = wid >> 2;                        // 0..1 m-half
#pragma unroll
        for (int jn = 0; jn < 4; jn++)
#pragma unroll
            for (int p = 0; p < 2; p++) {
                const int col = n0w + jn * 8 + 2 * lane + p;
                st[((mh * 128) + col) * 2 + 0] = cs[jn][p];
                st[((mh * 128) + col) * 2 + 1] = cq[jn][p];
            }
    }
    __syncthreads();
    {
        const int col  = tid >> 1;                      // 0..127
        const int stat = tid & 1;
        float v = st[col * 2 + stat] + st[(128 + col) * 2 + stat];
        if (stat == 0) g_psum[(size_t)(n0 + col) * NPART + bm] = v;
        else           g_psq [(size_t)(n0 + col) * NPART + bm] = v;
    }
}

// ---------------- Kernel 3: finalize mean / rstd (warp per channel) ----------
__global__ __launch_bounds__(256)
void stats_final()
{
    const int wid  = threadIdx.x >> 5;              // 0..7
    const int lane = threadIdx.x & 31;
    const int c = blockIdx.x * 8 + wid;             // grid 96 -> 768 channels

    const float* ps = &g_psum[(size_t)c * NPART];
    const float* pq = &g_psq [(size_t)c * NPART];
    double s = 0, q = 0;
#pragma unroll
    for (int j = 0; j < NPART / 32; j++) {
        s += (double)ps[lane + j * 32];
        q += (double)pq[lane + j * 32];
    }
#pragma unroll
    for (int r = 16; r >= 1; r >>= 1) {
        s += __shfl_xor_sync(0xffffffffu, s, r);
        q += __shfl_xor_sync(0xffffffffu, q, r);
    }
    if (lane == 0) {
        const double mean = s * (1.0 / 65536.0);
        const double var  = q * (1.0 / 65536.0) - mean * mean;
        const float varf = (float)var;
        g_mean[c] = (float)mean;
        g_rstd[c] = (float)(1.0 / sqrt((double)__fadd_rn(varf, 1e-5f)));
    }
}

// ---------------- Kernel 4: BN apply + LIF + fused 768x1024 transpose --------
// One batch per CTA (grid z = 16).  Each thread: one row, 4 consecutive q via
// LDG.128 (same per-element math & order as scalar version -> bit-identical).
__global__ __launch_bounds__(256)
void bn_lif_transpose(const float* __restrict__ gamma,
                      const float* __restrict__ beta,
                      float* __restrict__ out)
{
    __shared__ float sMean[CC];
    __shared__ float sRstd[CC];
    __shared__ float sGam[CC];
    __shared__ float sBet[CC];
    __shared__ float tile[T_STEPS][32][33];

    const int tid = threadIdx.x;
    for (int i = tid; i < CC; i += 256) {
        sMean[i] = g_mean[i];
        sRstd[i] = g_rstd[i];
        sGam[i]  = gamma[i];
        sBet[i]  = beta[i];
    }
    __syncthreads();

    const int b  = blockIdx.z;           // 0..15
    const int r0 = blockIdx.y * 32;      // 0..736 (24 tiles)
    const int q0 = blockIdx.x * 32;      // 0..992 (32 tiles)

    // ---- phase 1: each thread handles one row, 4 consecutive q --------------
    {
        const int qg = (tid & 7) * 4;                // 0,4,...,28
        const int rr = tid >> 3;                     // 0..31
        const int r  = r0 + rr;
        const int jb = r * 1024 + q0 + qg;           // 16B-aligned in g_y
        const int cb = jb % CC;                      // multiple of 4, no wrap

        float m[4], rs[4], ga[4], be[4];
#pragma unroll
        for (int e = 0; e < 4; e++) {
            m[e]  = sMean[cb + e];
            rs[e] = sRstd[cb + e];
            ga[e] = sGam[cb + e];
            be[e] = sBet[cb + e];
        }
        float v[4] = {0.f, 0.f, 0.f, 0.f};
#pragma unroll
        for (int t = 0; t < T_STEPS; t++) {
            const float4 y4 = *(const float4*)&g_y[(size_t)(t * B_SZ + b) * JBLK + jb];
            const float ye[4] = {y4.x, y4.y, y4.z, y4.w};
#pragma unroll
            for (int e = 0; e < 4; e++) {
                const float u = __fadd_rn(__fmul_rn(__fmul_rn(__fsub_rn(ye[e], m[e]), rs[e]), ga[e]), be[e]);
                v[e] = __fadd_rn(v[e], __fmul_rn(__fsub_rn(u, v[e]), 0.5f));  // v += (x-v)/2
                const float spk = (v[e] >= 1.0f) ? 1.0f : 0.0f;
                tile[t][rr][qg + e] = spk;
                v[e] = (v[e] >= 1.0f) ? 0.0f : v[e];                          // hard reset
            }
        }
    }
    __syncthreads();

    // ---- phase 2: transposed write-out (unchanged) ---------------------------
    {
        const int tx = tid & 31;
        const int ty = tid >> 5;                     // 0..7
#pragma unroll
        for (int qq = ty; qq < 32; qq += 8) {
            const size_t kidx = (size_t)(q0 + qq) * CC + r0 + tx;
#pragma unroll
            for (int t = 0; t < T_STEPS; t++) {
                out[(size_t)(t * B_SZ + b) * JBLK + kidx] = tile[t][tx][qq];
            }
        }
    }
}

// ---------------- launch ------------------------------------------------------
extern "C" void kernel_launch(void* const* d_in, const int* in_sizes, int n_in,
                              void* d_out, int out_size)
{
    const float* x     = (const float*)d_in[0];   // (64, 1024, 768)
    const float* W     = (const float*)d_in[1];   // (768, 768)
    const float* gamma = (const float*)d_in[2];   // (768,)
    const float* beta  = (const float*)d_in[3];   // (768,)
    float* out = (float*)d_out;                   // (64, 1024, 768)
    (void)in_sizes; (void)n_in; (void)out_size;

    cudaFuncSetAttribute(gemm_fused,
                         cudaFuncAttributeMaxDynamicSharedMemorySize, SMEM_GEMM);

    {   // split W into fp16 planes (tiny)
        const int n4w = CC * CC / 4;              // 147,456
        split2_w<<<(n4w + 255) / 256, 256>>>(W, n4w);
    }
    {
        dim3 grid(CC / GN, M_ROWS / GM);          // (6, 1024)
        gemm_fused<<<grid, NTHR, SMEM_GEMM>>>(x);
    }
    stats_final<<<96, 256>>>();
    {
        dim3 grid(NDIM / 32, CC / 32, B_SZ);      // (32, 24, 16)
        bn_lif_transpose<<<grid, 256>>>(gamma, beta, out);
    }
}

// round 17
// speedup vs baseline: 1.0055x; 1.0055x over previous
#include <cuda_runtime.h>
#include <cuda_fp16.h>
#include <cstdint>
#include <math.h>

// Problem dims (fixed by the dataset)
#define T_STEPS 4
#define B_SZ    16
#define TBDIM   64               // T*B
#define NDIM    1024
#define CC      768              // channels (in == out)
#define M_ROWS  (TBDIM * NDIM)   // 65536
#define JBLK    (NDIM * CC)      // 786432 elements per tb block

#define NPART 1024               // one stats partial per (channel, 64-row m-tile)

// ---------------- scratch (static device globals; no runtime alloc) ----------
__device__ float  g_y[(size_t)M_ROWS * CC];         // 201 MB GEMM output
__device__ __half g_wp[2][(size_t)CC * CC];         // 2.3 MB split planes of W
__device__ float  g_psum[CC * NPART];
__device__ float  g_psq [CC * NPART];
__device__ float  g_mean[CC];
__device__ float  g_rstd[CC];

// =================== low-level helpers (base ISA only) =======================
__device__ __forceinline__ uint32_t smem_u32(const void* p) {
    uint32_t a;
    asm("{ .reg .u64 t; cvta.to.shared.u64 t, %1; cvt.u32.u64 %0, t; }" : "=r"(a) : "l"(p));
    return a;
}
__device__ __forceinline__ uint32_t swz(uint32_t o) {   // SW128: XOR bits[6:4] ^= bits[9:7]
    return o ^ ((o >> 3) & 0x70);
}
__device__ __forceinline__ uint32_t h2u(__half2 h) {
    return *reinterpret_cast<uint32_t*>(&h);
}
#define CP_ASYNC16(dst, src) \
    asm volatile("cp.async.cg.shared.global [%0], [%1], 16;" :: "r"(dst), "l"(src))
#define CP_COMMIT() asm volatile("cp.async.commit_group;" ::: "memory")
#define CP_WAIT0()  asm volatile("cp.async.wait_group 0;" ::: "memory")

#define LDSM4(r, addr)                                                          \
    asm volatile("ldmatrix.sync.aligned.m8n8.x4.shared.b16 {%0,%1,%2,%3}, [%4];"\
        : "=r"((r)[0]), "=r"((r)[1]), "=r"((r)[2]), "=r"((r)[3]) : "r"(addr))

#define MMA16816(c, a, bb0, bb1)                                                \
    asm volatile("mma.sync.aligned.m16n8k16.row.col.f32.f16.f16.f32 "           \
                 "{%0,%1,%2,%3}, {%4,%5,%6,%7}, {%8,%9}, {%0,%1,%2,%3};"        \
        : "+f"((c)[0]), "+f"((c)[1]), "+f"((c)[2]), "+f"((c)[3])                \
        : "r"((a)[0]), "r"((a)[1]), "r"((a)[2]), "r"((a)[3]), "r"(bb0), "r"(bb1))

// =================== Kernel 0: exact 2-way fp16 split (W only) ===============
__global__ __launch_bounds__(256)
void split2_w(const float* __restrict__ src, int n4)
{
    const int i = blockIdx.x * 256 + threadIdx.x;
    if (i >= n4) return;
    const float4 v = ((const float4*)src)[i];
    float2 p0 = make_float2(v.x, v.y);
    float2 p1 = make_float2(v.z, v.w);
    __half2 a0 = __float22half2_rn(p0);
    __half2 a1 = __float22half2_rn(p1);
    float2 f0 = __half22float2(a0);
    float2 f1 = __half22float2(a1);
    float2 r0 = make_float2(__fsub_rn(p0.x, f0.x), __fsub_rn(p0.y, f0.y));
    float2 r1 = make_float2(__fsub_rn(p1.x, f1.x), __fsub_rn(p1.y, f1.y));
    __half2 b0 = __float22half2_rn(r0);
    __half2 b1 = __float22half2_rn(r1);
    ((uint2*)g_wp[0])[i] = make_uint2(h2u(a0), h2u(a1));
    ((uint2*)g_wp[1])[i] = make_uint2(h2u(b0), h2u(b1));
}

// =================== Kernel 1: fused split + fp16x3 GEMM + stats =============
// Y[m][n] = sum_k X[m][k] * W[n][k].  CTA tile 64x128 (M x N), 12 K-stages of 64.
// 256 threads, 8 warps, warp tile 32x32 (2x4 warp grid), 2 CTAs per SM.
#define GM 64
#define GN 128
#define NTHR 256
#define SM_A_OFF   0
#define SM_B_OFF   32768
#define SMEM_GEMM  98304        // 96 KB -> 2 CTAs/SM

__global__ __launch_bounds__(NTHR, 2)
void gemm_fused(const float* __restrict__ X)
{
    extern __shared__ __align__(1024) char smem[];
    const uint32_t sb = smem_u32(smem);
    const int tid  = threadIdx.x;
    const int lane = tid & 31;
    const int wid  = tid >> 5;          // 0..7

    const int n0 = blockIdx.x * GN;     // 0..5    -> channel strip
    const int m0 = blockIdx.y * GM;     // 0..1023 -> 64-row tile
    const int bm = blockIdx.y;
    const int m0w = (wid >> 2) * 32;    // warp tile 32x32 (2 m-halves)
    const int n0w = (wid & 3) * 32;

    float accM[2][4][4];
    float accT[2][4][4];
#pragma unroll
    for (int i = 0; i < 2; i++)
#pragma unroll
        for (int j = 0; j < 4; j++)
#pragma unroll
            for (int k = 0; k < 4; k++) { accM[i][j][k] = 0.f; accT[i][j][k] = 0.f; }

    // ---- strength-reduced base addresses ------------------------------------
    const int rA = m0w + (lane & 15);
    const uint32_t cA = (uint32_t)((lane >> 4) * 16);
    const int rB = n0w + (lane & 7) + ((lane >> 4) << 3);
    const uint32_t cB = (uint32_t)(((lane >> 3) & 1) * 16);
    const uint32_t swzA0 = swz((uint32_t)(rA * 128) + cA);
    const uint32_t swzB0 = swz((uint32_t)(rB * 128) + cB);

    // issueB: it 0..3 -> plane0 rows rowB0+32it; it 4..7 -> plane1 same rows
    const int chB   = tid & 7;
    const int rowB0 = (tid >> 3) & 127;              // 0..31
    const __half* srcB0 = &g_wp[0][(size_t)(n0 + rowB0) * CC + chB * 8];
    const __half* srcB1 = &g_wp[1][(size_t)(n0 + rowB0) * CC + chB * 8];
    const uint32_t dstB0 = swz((uint32_t)(rowB0 * 128 + chB * 16));  // +4096/it

    // ldgX / convert: it 0..3 -> rows rowX0+16it
    const int chX   = tid & 15;
    const int rowX0 = tid >> 4;                      // 0..15
    const float* srcX0 = &X[(size_t)(m0 + rowX0) * CC + chX * 4];
    const uint32_t dstA0 = swz((uint32_t)(rowX0 * 128 + chX * 8));   // +2048/it

    // ---- B planes via cp.async (strength-reduced addressing) ----
    auto issueB = [&](int k) {
        if (k <= 11) {
            const size_t koff = (size_t)(k * 64);
            const uint32_t bplb = sb + SM_B_OFF + (uint32_t)(k & 1) * 32768 + dstB0;
            const __half* s0 = srcB0 + koff;
            const __half* s1 = srcB1 + koff;
#pragma unroll
            for (int it = 0; it < 4; it++)
                CP_ASYNC16(bplb + (uint32_t)it * 4096, s0 + (size_t)it * 32 * CC);
#pragma unroll
            for (int it = 0; it < 4; it++)
                CP_ASYNC16(bplb + 16384u + (uint32_t)it * 4096, s1 + (size_t)it * 32 * CC);
        }
        CP_COMMIT();                                 // empty commits count too
    };

    // ---- X prefetch: 2 LDG.128 per call (half = 0 or 1) ----
    auto ldgX_half = [&](int s1, float4* xr, int half) {
        const float* s = srcX0 + (size_t)(s1 * 64);
#pragma unroll
        for (int it = half * 2; it < half * 2 + 2; it++)
            xr[it] = *(const float4*)(s + (size_t)it * 16 * CC);
    };

    // ---- packed split -> A1/A2 fp16 plane STS (bit-identical to scalar) -----
    auto convertStore = [&](int s1, const float4* xr) {
        char* ap = smem + SM_A_OFF + (size_t)(s1 & 1) * 16384;
#pragma unroll
        for (int it = 0; it < 4; it++) {
            float2 p0 = make_float2(xr[it].x, xr[it].y);
            float2 p1 = make_float2(xr[it].z, xr[it].w);
            __half2 a0 = __float22half2_rn(p0);
            __half2 a1 = __float22half2_rn(p1);
            float2 f0 = __half22float2(a0);
            float2 f1 = __half22float2(a1);
            float2 r0 = make_float2(__fsub_rn(p0.x, f0.x), __fsub_rn(p0.y, f0.y));
            float2 r1 = make_float2(__fsub_rn(p1.x, f1.x), __fsub_rn(p1.y, f1.y));
            __half2 b0 = __float22half2_rn(r0);
            __half2 b1 = __float22half2_rn(r1);
            const uint32_t o = dstA0 + (uint32_t)it * 2048;
            *(uint2*)(ap + o)        = make_uint2(h2u(a0), h2u(a1));
            *(uint2*)(ap + 8192 + o) = make_uint2(h2u(b0), h2u(b1));
        }
    };

    // ---- prologue ----
    float4 xreg[4];
    issueB(0);
    ldgX_half(0, xreg, 0);
    ldgX_half(0, xreg, 1);
    CP_WAIT0();            // B(0) done
    convertStore(0, xreg);

    // ---- main loop: LDG halves straddle the MMA block; convert after ----
    for (int s = 0; s < 12; s++) {
        __syncthreads();                   // A(s&1)/B(s&1) visible; WAR safe
        issueB(s + 1);                     // pending: s+1 only (ring2)
        if (s < 11) ldgX_half(s + 1, xreg, 0);

        const uint32_t aBase = sb + SM_A_OFF + (uint32_t)(s & 1) * 16384 + swzA0;
        const uint32_t bBase = sb + SM_B_OFF + (uint32_t)(s & 1) * 32768 + swzB0;

#pragma unroll
        for (int j = 0; j < 4; j++) {      // k16 steps within stage
            const uint32_t jo = (uint32_t)(j * 32);
            uint32_t a1[2][4], a2[2][4], b1f[2][4], b2f[2][4];
#pragma unroll
            for (int i = 0; i < 2; i++)
                LDSM4(a1[i], (aBase + (uint32_t)i * 2048) ^ jo);
#pragma unroll
            for (int h = 0; h < 2; h++) {
                LDSM4(b1f[h], (bBase + (uint32_t)h * 2048) ^ jo);
                LDSM4(b2f[h], (bBase + 16384u + (uint32_t)h * 2048) ^ jo);
            }
#pragma unroll
            for (int i = 0; i < 2; i++)
#pragma unroll
                for (int h = 0; h < 2; h++) {
                    MMA16816(accT[i][2 * h],     a1[i], b1f[h][0], b1f[h][1]);
                    MMA16816(accT[i][2 * h + 1], a1[i], b1f[h][2], b1f[h][3]);
                }
#pragma unroll
            for (int i = 0; i < 2; i++)
#pragma unroll
                for (int h = 0; h < 2; h++) {
                    MMA16816(accT[i][2 * h],     a1[i], b2f[h][0], b2f[h][1]);
                    MMA16816(accT[i][2 * h + 1], a1[i], b2f[h][2], b2f[h][3]);
                }
#pragma unroll
            for (int i = 0; i < 2; i++)
                LDSM4(a2[i], (aBase + 8192u + (uint32_t)i * 2048) ^ jo);
#pragma unroll
            for (int i = 0; i < 2; i++)
#pragma unroll
                for (int h = 0; h < 2; h++) {
                    MMA16816(accT[i][2 * h],     a2[i], b1f[h][0], b1f[h][1]);
                    MMA16816(accT[i][2 * h + 1], a2[i], b1f[h][2], b1f[h][3]);
                }
            if (j == 1 && s < 11) ldgX_half(s + 1, xreg, 1);
        }

        if (s < 11) convertStore(s + 1, xreg);   // regs already landed

        // fold stage partial into persistent accumulator (independent of cp.async)
#pragma unroll
        for (int i = 0; i < 2; i++)
#pragma unroll
            for (int jn = 0; jn < 4; jn++)
#pragma unroll
                for (int k = 0; k < 4; k++) {
                    accM[i][jn][k] = __fadd_rn(accM[i][jn][k], accT[i][jn][k]);
                    accT[i][jn][k] = 0.f;
                }

        CP_WAIT0();                              // B(s+1) landed
    }

    // ---- epilogue 1: store y ----
#pragma unroll
    for (int i = 0; i < 2; i++)
#pragma unroll
        for (int jn = 0; jn < 4; jn++) {
            const int row = m0 + m0w + i * 16 + (lane >> 2);
            const int col = n0 + n0w + jn * 8 + 2 * (lane & 3);
            float2 v0 = make_float2(accM[i][jn][0], accM[i][jn][1]);
            float2 v1 = make_float2(accM[i][jn][2], accM[i][jn][3]);
            *(float2*)&g_y[(size_t)row * CC + col]       = v0;
            *(float2*)&g_y[(size_t)(row + 8) * CC + col] = v1;
        }

    // ---- epilogue 2: per-column sum / sumsq over this CTA's 64 rows ---------
    float cs[4][2], cq[4][2];
#pragma unroll
    for (int jn = 0; jn < 4; jn++)
#pragma unroll
        for (int p = 0; p < 2; p++) { cs[jn][p] = 0.f; cq[jn][p] = 0.f; }
#pragma unroll
    for (int i = 0; i < 2; i++)
#pragma unroll
        for (int jn = 0; jn < 4; jn++) {
#pragma unroll
            for (int p = 0; p < 2; p++) {
                const float v0 = accM[i][jn][p];        // row lane>>2
                const float v1 = accM[i][jn][p + 2];    // row lane>>2 + 8
                cs[jn][p] += v0 + v1;
                cq[jn][p] = __fmaf_rn(v0, v0, cq[jn][p]);
                cq[jn][p] = __fmaf_rn(v1, v1, cq[jn][p]);
            }
        }
    // butterfly over the 8 lanes sharing (lane & 3): offsets 4, 8, 16
#pragma unroll
    for (int r = 4; r <= 16; r <<= 1)
#pragma unroll
        for (int jn = 0; jn < 4; jn++)
#pragma unroll
            for (int p = 0; p < 2; p++) {
                cs[jn][p] += __shfl_xor_sync(0xffffffffu, cs[jn][p], r);
                cq[jn][p] += __shfl_xor_sync(0xffffffffu, cq[jn][p], r);
            }
    // stage per-warp column sums in smem (reuse A-plane area; idle now)
    float* st = (float*)(smem + SM_A_OFF);              // [2][128][2]
    __syncthreads();                                    // all MMA/convert done
    if (lane < 4) {
        const int mh = wid >> 2;                        // 0..1 m-half
#pragma unroll
        for (int jn = 0; jn < 4; jn++)
#pragma unroll
            for (int p = 0; p < 2; p++) {
                const int col = n0w + jn * 8 + 2 * lane + p;
                st[((mh * 128) + col) * 2 + 0] = cs[jn][p];
                st[((mh * 128) + col) * 2 + 1] = cq[jn][p];
            }
    }
    __syncthreads();
    {
        const int col  = tid >> 1;                      // 0..127
        const int stat = tid & 1;
        float v = st[col * 2 + stat] + st[(128 + col) * 2 + stat];
        if (stat == 0) g_psum[(size_t)(n0 + col) * NPART + bm] = v;
        else           g_psq [(size_t)(n0 + col) * NPART + bm] = v;
    }
}

// ---------------- Kernel 3: finalize mean / rstd (warp per channel) ----------
__global__ __launch_bounds__(256)
void stats_final()
{
    const int wid  = threadIdx.x >> 5;              // 0..7
    const int lane = threadIdx.x & 31;
    const int c = blockIdx.x * 8 + wid;             // grid 96 -> 768 channels

    const float* ps = &g_psum[(size_t)c * NPART];
    const float* pq = &g_psq [(size_t)c * NPART];
    double s = 0, q = 0;
#pragma unroll
    for (int j = 0; j < NPART / 32; j++) {
        s += (double)ps[lane + j * 32];
        q += (double)pq[lane + j * 32];
    }
#pragma unroll
    for (int r = 16; r >= 1; r >>= 1) {
        s += __shfl_xor_sync(0xffffffffu, s, r);
        q += __shfl_xor_sync(0xffffffffu, q, r);
    }
    if (lane == 0) {
        const double mean = s * (1.0 / 65536.0);
        const double var  = q * (1.0 / 65536.0) - mean * mean;
        const float varf = (float)var;
        g_mean[c] = (float)mean;
        g_rstd[c] = (float)(1.0 / sqrt((double)__fadd_rn(varf, 1e-5f)));
    }
}

// ---------------- Kernel 4: BN apply + LIF + fused 768x1024 transpose --------
// One batch per CTA (grid z = 16).  Phase 1: scalar loads (high MLP, R15 form).
// Phase 2: float4 stores along r (same values, same addresses -> bit-identical).
__global__ __launch_bounds__(256)
void bn_lif_transpose(const float* __restrict__ gamma,
                      const float* __restrict__ beta,
                      float* __restrict__ out)
{
    __shared__ float sMean[CC];
    __shared__ float sRstd[CC];
    __shared__ float sGam[CC];
    __shared__ float sBet[CC];
    __shared__ float tile[T_STEPS][32][33];

    const int tid = threadIdx.x;
    for (int i = tid; i < CC; i += 256) {
        sMean[i] = g_mean[i];
        sRstd[i] = g_rstd[i];
        sGam[i]  = gamma[i];
        sBet[i]  = beta[i];
    }
    __syncthreads();

    const int b  = blockIdx.z;           // 0..15
    const int r0 = blockIdx.y * 32;      // 0..736 (24 tiles)
    const int q0 = blockIdx.x * 32;      // 0..992 (32 tiles)
    const int tx = tid & 31;
    const int ty = tid >> 5;             // 0..7

    // ---- phase 1: scalar loads, 4 rows x 4 t per thread (MLP = 16) ----------
#pragma unroll
    for (int rr = ty; rr < 32; rr += 8) {
        const int r = r0 + rr;
        const int j = r * 1024 + q0 + tx;
        const int c = j % CC;
        const float m  = sMean[c];
        const float rs = sRstd[c];
        const float ga = sGam[c];
        const float be = sBet[c];
        float v = 0.f;
#pragma unroll
        for (int t = 0; t < T_STEPS; t++) {
            const float yv = g_y[(size_t)(t * B_SZ + b) * JBLK + j];
            const float u = __fadd_rn(__fmul_rn(__fmul_rn(__fsub_rn(yv, m), rs), ga), be);
            v = __fadd_rn(v, __fmul_rn(__fsub_rn(u, v), 0.5f));   // v += (x - v)/2
            const float spk = (v >= 1.0f) ? 1.0f : 0.0f;
            tile[t][rr][tx] = spk;
            v = (v >= 1.0f) ? 0.0f : v;                           // hard reset
        }
    }
    __syncthreads();

    // ---- phase 2: float4 stores along r (4 r per thread, 1 q) ---------------
    {
        const int r4 = (tid & 7) * 4;                // 0,4,...,28
        const int qq = tid >> 3;                     // 0..31
        const size_t kbase = (size_t)(q0 + qq) * CC + r0 + r4;   // 16B aligned
#pragma unroll
        for (int t = 0; t < T_STEPS; t++) {
            float4 v = make_float4(tile[t][r4 + 0][qq], tile[t][r4 + 1][qq],
                                   tile[t][r4 + 2][qq], tile[t][r4 + 3][qq]);
            *(float4*)&out[(size_t)(t * B_SZ + b) * JBLK + kbase] = v;
        }
    }
}

// ---------------- launch ------------------------------------------------------
extern "C" void kernel_launch(void* const* d_in, const int* in_sizes, int n_in,
                              void* d_out, int out_size)
{
    const float* x     = (const float*)d_in[0];   // (64, 1024, 768)
    const float* W     = (const float*)d_in[1];   // (768, 768)
    const float* gamma = (const float*)d_in[2];   // (768,)
    const float* beta  = (const float*)d_in[3];   // (768,)
    float* out = (float*)d_out;                   // (64, 1024, 768)
    (void)in_sizes; (void)n_in; (void)out_size;

    cudaFuncSetAttribute(gemm_fused,
                         cudaFuncAttributeMaxDynamicSharedMemorySize, SMEM_GEMM);

    {   // split W into fp16 planes (tiny)
        const int n4w = CC * CC / 4;              // 147,456
        split2_w<<<(n4w + 255) / 256, 256>>>(W, n4w);
    }
    {
        dim3 grid(CC / GN, M_ROWS / GM);          // (6, 1024)
        gemm_fused<<<grid, NTHR, SMEM_GEMM>>>(x);
    }
    stats_final<<<96, 256>>>();
    {
        dim3 grid(NDIM / 32, CC / 32, B_SZ);      // (32, 24, 16)
        bn_lif_transpose<<<grid, 256>>>(gamma, beta, out);
    }
}